// round 16
// baseline (speedup 1.0000x reference)
#include <cuda_runtime.h>
#include <cstdint>
#include <cstddef>

#define NB      64
#define NPRED   100800
#define KDET    512
#define CAP     8192
#define SEL     1024
#define CONF_T  0.7f
#define IOU_T   0.45f

#define K1_THREADS 256
#define K1_RPT     8                       // rows per thread
#define K1_ROWS    (K1_THREADS * K1_RPT)   // 2048
#define K1_BLKS    50                      // 50*2048 >= 100800

#define MB_SPLIT 4                         // row-stride split of mask columns

// Global scratch (__device__ arrays; no allocation).
__device__ float    g_sc[NB][CAP];
__device__ int      g_ix[NB][CAP];
__device__ int      g_cnt[NB];            // zero at load; reset by select_sort
__device__ float4   g_boxes[NB][KDET];
__device__ float    g_area[NB][KDET];
__device__ float    g_ssc[NB][KDET];
__device__ int      g_six[NB][KDET];
__device__ unsigned g_kw[NB][16];
// Zero-initialized; words never written below stay 0 forever (incl. replays).
__device__ unsigned g_mask[NB][KDET * 16];  // 2 MB

// ---------------------------------------------------------------------------
// Kernel 1: direct-LDG scoring + two-level compaction (unchanged).
// ---------------------------------------------------------------------------
__global__ __launch_bounds__(K1_THREADS)
void score_compact_kernel(const float* __restrict__ pred) {
    __shared__ float stg_sc[256];
    __shared__ int   stg_ix[256];
    __shared__ int   sCnt, blockBase;

    const int b   = blockIdx.y;
    const int tid = threadIdx.x;
    const int r0  = blockIdx.x * K1_ROWS;
    if (tid == 0) sCnt = 0;
    __syncthreads();

    const float* __restrict__ base = pred + (size_t)b * NPRED * 9;

    float a[K1_RPT], c[K1_RPT];
    int   rr[K1_RPT];
    #pragma unroll
    for (int k = 0; k < K1_RPT; k++) {          // front-batched loads (MLP 16)
        int r = r0 + k * K1_THREADS + tid;      // coalesced within each k
        rr[k] = r;
        bool ok = r < NPRED;
        const float* p = base + (size_t)r * 9;
        a[k] = ok ? __ldg(p + 4) : 0.0f;
        c[k] = ok ? __ldg(p + 5) : 0.0f;
    }
    #pragma unroll
    for (int k = 0; k < K1_RPT; k++) {
        float conf = __fmul_rn(a[k], c[k]);     // exact, matches reference
        if (conf > CONF_T) {
            int p = atomicAdd(&sCnt, 1);        // ~100 per block
            if (p < 256) { stg_sc[p] = conf; stg_ix[p] = rr[k]; }
        }
    }
    __syncthreads();
    if (tid == 0) blockBase = atomicAdd(&g_cnt[b], sCnt);   // ONE global atomic
    __syncthreads();

    int n = min(sCnt, 256);
    int gbase = blockBase;
    for (int t = tid; t < n; t += K1_THREADS) {
        int p = gbase + t;
        if (p < CAP) { g_sc[b][p] = stg_sc[t]; g_ix[b][p] = stg_ix[t]; }
    }
}

// ---------------------------------------------------------------------------
// Kernel 2a: radix-select (warp-shfl suffix scan, warp-aggregated collection
// with WARP-UNIFORM trip count) + hybrid bitonic(1024).
// ---------------------------------------------------------------------------
__global__ __launch_bounds__(1024, 1)
void select_sort_kernel(const float* __restrict__ pred) {
    __shared__ float bufS[2][SEL];     // 8 KB (double-buffer)
    __shared__ int   bufI[2][SEL];     // 8 KB
    __shared__ int   hist[1024];       // 4 KB
    __shared__ int   warpOff[32];
    __shared__ int   selCnt, b1s;

    const int tid  = threadIdx.x;
    const int lane = tid & 31;
    const int wrp  = tid >> 5;
    const int b    = blockIdx.x;
    int cnt = g_cnt[b];
    if (cnt > CAP) cnt = CAP;

    // Phase 1: histogram on score bits [22:13] (exponent fixed for (0.7,1))
    hist[tid] = 0;
    if (tid == 0) { selCnt = 0; b1s = -1; }
    __syncthreads();
    for (int e = tid; e < cnt; e += 1024) {
        unsigned u = __float_as_uint(g_sc[b][e]);
        atomicAdd(&hist[(u >> 13) & 1023], 1);
    }
    __syncthreads();

    // Phase 2: hierarchical inclusive SUFFIX scan (3 barriers)
    int val = hist[tid];
    #pragma unroll
    for (int d = 1; d < 32; d <<= 1) {
        int v = __shfl_down_sync(0xffffffffu, val, d);
        if (lane + d < 32) val += v;
    }
    if (lane == 0) warpOff[wrp] = val;          // warp total
    __syncthreads();
    if (wrp == 0) {
        int t = warpOff[lane];
        int tot = t;
        #pragma unroll
        for (int d = 1; d < 32; d <<= 1) {
            int v = __shfl_down_sync(0xffffffffu, tot, d);
            if (lane + d < 32) tot += v;
        }
        warpOff[lane] = tot - t;                // exclusive suffix of warp totals
    }
    __syncthreads();
    int suffix = val + warpOff[wrp];            // sum of hist[u] for u >= tid
    int target = (cnt < KDET) ? cnt : KDET;
    if (suffix >= target) atomicMax(&b1s, tid);
    __syncthreads();
    int b1 = b1s;

    // Phase 3: collect bins >= b1, warp-aggregated, UNIFORM trip count.
    // All 32 lanes execute every iteration (guard is block-uniform e0<cnt),
    // so every lane reaches each __ballot_sync. Intra-warp order is
    // lane-ordered; Phase 4's full sort canonicalizes order either way.
    for (int e0 = 0; e0 < cnt; e0 += 1024) {
        int e = e0 + tid;
        bool hit = false;
        float sc = 0.0f;
        if (e < cnt) {
            sc = g_sc[b][e];
            hit = (int)((__float_as_uint(sc) >> 13) & 1023) >= b1;
        }
        unsigned m = __ballot_sync(0xffffffffu, hit);
        if (m) {
            int leader = __ffs(m) - 1;
            int base;
            if (lane == leader) base = atomicAdd(&selCnt, __popc(m));
            base = __shfl_sync(0xffffffffu, base, leader);
            if (hit) {
                int p = base + __popc(m & ((1u << lane) - 1u));
                if (p < SEL) { bufS[0][p] = sc; bufI[0][p] = g_ix[b][e]; }
            }
        }
    }
    __syncthreads();
    int selN = selCnt; if (selN > SEL) selN = SEL;
    if (tid >= selN) { bufS[0][tid] = -1.0f; bufI[0][tid] = 0x7fffffff; }
    __syncthreads();

    // Phase 4: hybrid bitonic sort (score desc, idx asc == lax.top_k order)
    float s  = bufS[0][tid];
    int   ix = bufI[0][tid];
    int   pb = 1;
    for (int k = 2; k <= SEL; k <<= 1) {
        for (int j = k >> 1; j > 0; j >>= 1) {
            float s2; int i2;
            if (j >= 32) {
                bufS[pb][tid] = s; bufI[pb][tid] = ix;
                __syncthreads();
                s2 = bufS[pb][tid ^ j]; i2 = bufI[pb][tid ^ j];
                pb ^= 1;
            } else {
                s2 = __shfl_xor_sync(0xffffffffu, s, j);
                i2 = __shfl_xor_sync(0xffffffffu, ix, j);
            }
            bool want_first = ((tid & k) == 0);
            bool i_low      = ((tid & j) == 0);
            bool mine_better = (s > s2) || (s == s2 && ix < i2);
            if (mine_better != (i_low == want_first)) { s = s2; ix = i2; }
        }
    }

    // Phase 5: gather top-512 rows -> boxes/areas/validity, store to global.
    if (tid < KDET) {
        float4 bx = make_float4(0.f, 0.f, 0.f, 0.f);
        float  ar = 0.f;
        bool valid = s > CONF_T;
        if (valid) {
            const float* r = pred + ((size_t)b * NPRED + ix) * 9;
            float cx = r[0], cy = r[1];
            float hw = __fmul_rn(r[2], 0.5f);     // exact; matches ref rounding
            float hh = __fmul_rn(r[3], 0.5f);
            bx.x = __fsub_rn(cx, hw); bx.y = __fsub_rn(cy, hh);
            bx.z = __fadd_rn(cx, hw); bx.w = __fadd_rn(cy, hh);
            ar = __fmul_rn(__fsub_rn(bx.z, bx.x), __fsub_rn(bx.w, bx.y));
        }
        g_boxes[b][tid] = bx;
        g_area[b][tid]  = ar;
        g_ssc[b][tid]   = s;
        g_six[b][tid]   = ix;
        unsigned bal = __ballot_sync(0xffffffffu, valid);
        if (lane == 0) g_kw[b][tid >> 5] = ~bal;  // removed-init = !valid
    }
    if (tid == 0) g_cnt[b] = 0;   // reset for next graph replay
}

// ---------------------------------------------------------------------------
// Kernel 2b: IoU mask, COLUMN-transposed. Warp q owns word-columns {q, 15-q}
// (pair = 544 rows, perfectly balanced); bj/aj live in registers for the whole
// column. Rows strided by MB_SPLIT across blockIdx.x. Row i writes word w only
// when i <= 32w+30 (word contains some j > i); other words stay zero-init.
// All inner-loop bounds are warp-uniform -> ballots are convergence-safe.
// ---------------------------------------------------------------------------
__global__ __launch_bounds__(256)
void mask_kernel() {
    __shared__ float4 Sb[KDET];    // 8 KB
    __shared__ float  Sa[KDET];    // 2 KB
    const int tid     = threadIdx.x;
    const int lane    = tid & 31;
    const int q       = tid >> 5;        // warp 0..7 -> column pair (q, 15-q)
    const int quarter = blockIdx.x;      // 0..MB_SPLIT-1 row stride phase
    const int b       = blockIdx.y;

    for (int t = tid; t < KDET; t += 256) { Sb[t] = g_boxes[b][t]; Sa[t] = g_area[b][t]; }
    __syncthreads();

    #pragma unroll
    for (int half = 0; half < 2; half++) {
        const int w = half ? (15 - q) : q;
        const int j = (w << 5) + lane;
        const float4 bj = Sb[j];             // register-resident for whole column
        const float  aj = Sa[j];
        unsigned* mcol = &g_mask[b][w];
        const int imax = (w << 5) + 30;      // last row with any j > i in word w
        #pragma unroll 1
        for (int i = quarter; i <= imax; i += MB_SPLIT) {
            float4 bi = Sb[i];               // LDS broadcast (N=1)
            float  ai = Sa[i];
            float xx1 = fmaxf(bi.x, bj.x), yy1 = fmaxf(bi.y, bj.y);
            float xx2 = fminf(bi.z, bj.z), yy2 = fminf(bi.w, bj.w);
            float iw = fmaxf(__fsub_rn(xx2, xx1), 0.f);
            float ih = fmaxf(__fsub_rn(yy2, yy1), 0.f);
            float inter = __fmul_rn(iw, ih);
            float denom = __fadd_rn(__fsub_rn(__fadd_rn(ai, aj), inter), 1e-7f);
            float t45 = __fmul_rn(denom, IOU_T);
            bool over;
            if      (inter > __fmul_rn(t45, 1.0000005f)) over = true;
            else if (inter < __fmul_rn(t45, 0.9999995f)) over = false;
            else    over = (__fdiv_rn(inter, denom) > IOU_T);   // exact fallback
            unsigned bits = __ballot_sync(0xffffffffu, over && (j > i));
            if (lane == 0) mcol[i << 4] = bits;
        }
    }
}

// ---------------------------------------------------------------------------
// Kernel 2c: warp-cooperative greedy suppression + output (unchanged).
// ---------------------------------------------------------------------------
__global__ __launch_bounds__(512)
void greedy_out_kernel(const float* __restrict__ pred, float* __restrict__ out) {
    __shared__ unsigned Sm[KDET * 16];   // 32 KB
    __shared__ unsigned Skw[16];
    const int tid  = threadIdx.x;
    const int lane = tid & 31;
    const int b    = blockIdx.x;

    {   // stage mask into smem, coalesced uint4
        const uint4* src = (const uint4*)g_mask[b];
        uint4* dst = (uint4*)Sm;
        #pragma unroll
        for (int u = 0; u < 4; u++) dst[tid + 512 * u] = src[tid + 512 * u];
    }
    if (tid < 16) Skw[tid] = g_kw[b][tid];
    __syncthreads();

    // Warp 0: greedy scan. Lane l (mirrored at l+16) owns removed-word l&15.
    if (tid < 32) {
        const int l16 = lane & 15;
        unsigned rem = Skw[l16];
        const unsigned* rowp = Sm + l16;       // this lane's mask column
        #pragma unroll 1
        for (int wb = 0; wb < 16; wb++) {
            unsigned cur = __shfl_sync(0xffffffffu, rem, wb);  // word wb tracker
            const unsigned* curp = Sm + wb;
            const int ib = wb << 5;
            unsigned prA = rowp[(ib + 0) << 4];
            unsigned pcA = curp[(ib + 0) << 4];
            unsigned prB = rowp[(ib + 1) << 4];
            unsigned pcB = curp[(ib + 1) << 4];
            #pragma unroll
            for (int bit = 0; bit < 32; bit++) {
                unsigned row = prA, cw = pcA;
                prA = prB; pcA = pcB;
                int nx = bit + 2; if (nx > 31) nx = 31;
                prB = rowp[(ib + nx) << 4];
                pcB = curp[(ib + nx) << 4];
                if (!((cur >> bit) & 1u)) {    // box ib+bit survives -> suppress
                    rem |= row;
                    cur |= cw;
                }
            }
        }
        if (lane < 16) Skw[lane] = rem;
    }
    __syncthreads();

    // Output [b, KDET, 9]; loads gated by kept (issued post-barrier)
    bool kept = !((Skw[tid >> 5] >> (tid & 31)) & 1u);
    float* orow = out + ((size_t)b * KDET + tid) * 9;
    if (kept) {
        float4 bx = g_boxes[b][tid];
        const float* r = pred + ((size_t)b * NPRED + g_six[b][tid]) * 9;
        orow[0] = bx.x; orow[1] = bx.y; orow[2] = bx.z; orow[3] = bx.w;
        orow[4] = g_ssc[b][tid];
        orow[5] = 0.0f;
        orow[6] = r[6]; orow[7] = r[7]; orow[8] = r[8];
    } else {
        #pragma unroll
        for (int q = 0; q < 9; q++) orow[q] = 0.0f;
    }
}

// ---------------------------------------------------------------------------
extern "C" void kernel_launch(void* const* d_in, const int* in_sizes, int n_in,
                              void* d_out, int out_size) {
    const float* pred = (const float*)d_in[0];
    float* out = (float*)d_out;

    score_compact_kernel<<<dim3(K1_BLKS, NB), K1_THREADS>>>(pred);
    select_sort_kernel<<<NB, 1024>>>(pred);
    mask_kernel<<<dim3(MB_SPLIT, NB), 256>>>();
    greedy_out_kernel<<<NB, KDET>>>(pred, out);
}

// round 17
// speedup vs baseline: 1.0008x; 1.0008x over previous
#include <cuda_runtime.h>
#include <cstdint>
#include <cstddef>

#define NB      64
#define NPRED   100800
#define KDET    512
#define CAP     8192
#define SEL     1024
#define CONF_T  0.7f
#define IOU_T   0.45f

#define K1_THREADS 256
#define K1_RPT     8                       // rows per thread
#define K1_ROWS    (K1_THREADS * K1_RPT)   // 2048
#define K1_BLKS    50                      // 50*2048 >= 100800

#define MB_SPLIT 4                         // row-stride split of mask columns

// Global scratch (__device__ arrays; no allocation).
__device__ float    g_sc[NB][CAP];
__device__ int      g_ix[NB][CAP];
__device__ int      g_cnt[NB];            // zero at load; reset by select_sort
__device__ float4   g_boxes[NB][KDET];
__device__ float    g_area[NB][KDET];
__device__ float    g_ssc[NB][KDET];
__device__ int      g_six[NB][KDET];
__device__ unsigned g_kw[NB][16];
// Zero-initialized; words never written below stay 0 forever (incl. replays).
__device__ unsigned g_mask[NB][KDET * 16];  // 2 MB

// ---------------------------------------------------------------------------
// Kernel 1: direct-LDG scoring + two-level compaction (unchanged).
// ---------------------------------------------------------------------------
__global__ __launch_bounds__(K1_THREADS)
void score_compact_kernel(const float* __restrict__ pred) {
    __shared__ float stg_sc[256];
    __shared__ int   stg_ix[256];
    __shared__ int   sCnt, blockBase;

    const int b   = blockIdx.y;
    const int tid = threadIdx.x;
    const int r0  = blockIdx.x * K1_ROWS;
    if (tid == 0) sCnt = 0;
    __syncthreads();

    const float* __restrict__ base = pred + (size_t)b * NPRED * 9;

    float a[K1_RPT], c[K1_RPT];
    int   rr[K1_RPT];
    #pragma unroll
    for (int k = 0; k < K1_RPT; k++) {          // front-batched loads (MLP 16)
        int r = r0 + k * K1_THREADS + tid;      // coalesced within each k
        rr[k] = r;
        bool ok = r < NPRED;
        const float* p = base + (size_t)r * 9;
        a[k] = ok ? __ldg(p + 4) : 0.0f;
        c[k] = ok ? __ldg(p + 5) : 0.0f;
    }
    #pragma unroll
    for (int k = 0; k < K1_RPT; k++) {
        float conf = __fmul_rn(a[k], c[k]);     // exact, matches reference
        if (conf > CONF_T) {
            int p = atomicAdd(&sCnt, 1);        // ~100 per block
            if (p < 256) { stg_sc[p] = conf; stg_ix[p] = rr[k]; }
        }
    }
    __syncthreads();
    if (tid == 0) blockBase = atomicAdd(&g_cnt[b], sCnt);   // ONE global atomic
    __syncthreads();

    int n = min(sCnt, 256);
    int gbase = blockBase;
    for (int t = tid; t < n; t += K1_THREADS) {
        int p = gbase + t;
        if (p < CAP) { g_sc[b][p] = stg_sc[t]; g_ix[b][p] = stg_ix[t]; }
    }
}

// ---------------------------------------------------------------------------
// Kernel 2a: radix-select (warp-shfl suffix scan) + hybrid bitonic(1024).
// Phase 3 reverted to round-10 simple-atomic collection (measured good).
// ---------------------------------------------------------------------------
__global__ __launch_bounds__(1024, 1)
void select_sort_kernel(const float* __restrict__ pred) {
    __shared__ float bufS[2][SEL];     // 8 KB (double-buffer)
    __shared__ int   bufI[2][SEL];     // 8 KB
    __shared__ int   hist[1024];       // 4 KB
    __shared__ int   warpOff[32];
    __shared__ int   selCnt, b1s;

    const int tid  = threadIdx.x;
    const int lane = tid & 31;
    const int wrp  = tid >> 5;
    const int b    = blockIdx.x;
    int cnt = g_cnt[b];
    if (cnt > CAP) cnt = CAP;

    // Phase 1: histogram on score bits [22:13] (exponent fixed for (0.7,1))
    hist[tid] = 0;
    if (tid == 0) { selCnt = 0; b1s = -1; }
    __syncthreads();
    for (int e = tid; e < cnt; e += 1024) {
        unsigned u = __float_as_uint(g_sc[b][e]);
        atomicAdd(&hist[(u >> 13) & 1023], 1);
    }
    __syncthreads();

    // Phase 2: hierarchical inclusive SUFFIX scan (3 barriers)
    int val = hist[tid];
    #pragma unroll
    for (int d = 1; d < 32; d <<= 1) {
        int v = __shfl_down_sync(0xffffffffu, val, d);
        if (lane + d < 32) val += v;
    }
    if (lane == 0) warpOff[wrp] = val;          // warp total
    __syncthreads();
    if (wrp == 0) {
        int t = warpOff[lane];
        int tot = t;
        #pragma unroll
        for (int d = 1; d < 32; d <<= 1) {
            int v = __shfl_down_sync(0xffffffffu, tot, d);
            if (lane + d < 32) tot += v;
        }
        warpOff[lane] = tot - t;                // exclusive suffix of warp totals
    }
    __syncthreads();
    int suffix = val + warpOff[wrp];            // sum of hist[u] for u >= tid
    int target = (cnt < KDET) ? cnt : KDET;
    if (suffix >= target) atomicMax(&b1s, tid);
    __syncthreads();
    int b1 = b1s;

    // Phase 3: collect bins >= b1 (round-10 version: plain smem atomic)
    for (int e = tid; e < cnt; e += 1024) {
        float sc = g_sc[b][e];
        if ((int)((__float_as_uint(sc) >> 13) & 1023) >= b1) {
            int p = atomicAdd(&selCnt, 1);
            if (p < SEL) { bufS[0][p] = sc; bufI[0][p] = g_ix[b][e]; }
        }
    }
    __syncthreads();
    int selN = selCnt; if (selN > SEL) selN = SEL;
    if (tid >= selN) { bufS[0][tid] = -1.0f; bufI[0][tid] = 0x7fffffff; }
    __syncthreads();

    // Phase 4: hybrid bitonic sort (score desc, idx asc == lax.top_k order)
    float s  = bufS[0][tid];
    int   ix = bufI[0][tid];
    int   pb = 1;
    for (int k = 2; k <= SEL; k <<= 1) {
        for (int j = k >> 1; j > 0; j >>= 1) {
            float s2; int i2;
            if (j >= 32) {
                bufS[pb][tid] = s; bufI[pb][tid] = ix;
                __syncthreads();
                s2 = bufS[pb][tid ^ j]; i2 = bufI[pb][tid ^ j];
                pb ^= 1;
            } else {
                s2 = __shfl_xor_sync(0xffffffffu, s, j);
                i2 = __shfl_xor_sync(0xffffffffu, ix, j);
            }
            bool want_first = ((tid & k) == 0);
            bool i_low      = ((tid & j) == 0);
            bool mine_better = (s > s2) || (s == s2 && ix < i2);
            if (mine_better != (i_low == want_first)) { s = s2; ix = i2; }
        }
    }

    // Phase 5: gather top-512 rows -> boxes/areas/validity, store to global.
    if (tid < KDET) {
        float4 bx = make_float4(0.f, 0.f, 0.f, 0.f);
        float  ar = 0.f;
        bool valid = s > CONF_T;
        if (valid) {
            const float* r = pred + ((size_t)b * NPRED + ix) * 9;
            float cx = r[0], cy = r[1];
            float hw = __fmul_rn(r[2], 0.5f);     // exact; matches ref rounding
            float hh = __fmul_rn(r[3], 0.5f);
            bx.x = __fsub_rn(cx, hw); bx.y = __fsub_rn(cy, hh);
            bx.z = __fadd_rn(cx, hw); bx.w = __fadd_rn(cy, hh);
            ar = __fmul_rn(__fsub_rn(bx.z, bx.x), __fsub_rn(bx.w, bx.y));
        }
        g_boxes[b][tid] = bx;
        g_area[b][tid]  = ar;
        g_ssc[b][tid]   = s;
        g_six[b][tid]   = ix;
        unsigned bal = __ballot_sync(0xffffffffu, valid);
        if (lane == 0) g_kw[b][tid >> 5] = ~bal;  // removed-init = !valid
    }
    if (tid == 0) g_cnt[b] = 0;   // reset for next graph replay
}

// ---------------------------------------------------------------------------
// Kernel 2b: IoU mask, COLUMN-transposed (change A, kept for isolated test).
// Warp q owns word-columns {q, 15-q} (pair = 544 rows, balanced); bj/aj in
// registers per column. Rows strided by MB_SPLIT across blockIdx.x. Words
// with no j > i are never written; static zero-init keeps them 0 on replays.
// ---------------------------------------------------------------------------
__global__ __launch_bounds__(256)
void mask_kernel() {
    __shared__ float4 Sb[KDET];    // 8 KB
    __shared__ float  Sa[KDET];    // 2 KB
    const int tid     = threadIdx.x;
    const int lane    = tid & 31;
    const int q       = tid >> 5;        // warp 0..7 -> column pair (q, 15-q)
    const int quarter = blockIdx.x;      // 0..MB_SPLIT-1 row stride phase
    const int b       = blockIdx.y;

    for (int t = tid; t < KDET; t += 256) { Sb[t] = g_boxes[b][t]; Sa[t] = g_area[b][t]; }
    __syncthreads();

    #pragma unroll
    for (int half = 0; half < 2; half++) {
        const int w = half ? (15 - q) : q;
        const int j = (w << 5) + lane;
        const float4 bj = Sb[j];             // register-resident for whole column
        const float  aj = Sa[j];
        unsigned* mcol = &g_mask[b][w];
        const int imax = (w << 5) + 30;      // last row with any j > i in word w
        #pragma unroll 1
        for (int i = quarter; i <= imax; i += MB_SPLIT) {
            float4 bi = Sb[i];               // LDS broadcast (N=1)
            float  ai = Sa[i];
            float xx1 = fmaxf(bi.x, bj.x), yy1 = fmaxf(bi.y, bj.y);
            float xx2 = fminf(bi.z, bj.z), yy2 = fminf(bi.w, bj.w);
            float iw = fmaxf(__fsub_rn(xx2, xx1), 0.f);
            float ih = fmaxf(__fsub_rn(yy2, yy1), 0.f);
            float inter = __fmul_rn(iw, ih);
            float denom = __fadd_rn(__fsub_rn(__fadd_rn(ai, aj), inter), 1e-7f);
            float t45 = __fmul_rn(denom, IOU_T);
            bool over;
            if      (inter > __fmul_rn(t45, 1.0000005f)) over = true;
            else if (inter < __fmul_rn(t45, 0.9999995f)) over = false;
            else    over = (__fdiv_rn(inter, denom) > IOU_T);   // exact fallback
            unsigned bits = __ballot_sync(0xffffffffu, over && (j > i));
            if (lane == 0) mcol[i << 4] = bits;
        }
    }
}

// ---------------------------------------------------------------------------
// Kernel 2c: warp-cooperative greedy suppression + output (unchanged).
// ---------------------------------------------------------------------------
__global__ __launch_bounds__(512)
void greedy_out_kernel(const float* __restrict__ pred, float* __restrict__ out) {
    __shared__ unsigned Sm[KDET * 16];   // 32 KB
    __shared__ unsigned Skw[16];
    const int tid  = threadIdx.x;
    const int lane = tid & 31;
    const int b    = blockIdx.x;

    {   // stage mask into smem, coalesced uint4
        const uint4* src = (const uint4*)g_mask[b];
        uint4* dst = (uint4*)Sm;
        #pragma unroll
        for (int u = 0; u < 4; u++) dst[tid + 512 * u] = src[tid + 512 * u];
    }
    if (tid < 16) Skw[tid] = g_kw[b][tid];
    __syncthreads();

    // Warp 0: greedy scan. Lane l (mirrored at l+16) owns removed-word l&15.
    if (tid < 32) {
        const int l16 = lane & 15;
        unsigned rem = Skw[l16];
        const unsigned* rowp = Sm + l16;       // this lane's mask column
        #pragma unroll 1
        for (int wb = 0; wb < 16; wb++) {
            unsigned cur = __shfl_sync(0xffffffffu, rem, wb);  // word wb tracker
            const unsigned* curp = Sm + wb;
            const int ib = wb << 5;
            unsigned prA = rowp[(ib + 0) << 4];
            unsigned pcA = curp[(ib + 0) << 4];
            unsigned prB = rowp[(ib + 1) << 4];
            unsigned pcB = curp[(ib + 1) << 4];
            #pragma unroll
            for (int bit = 0; bit < 32; bit++) {
                unsigned row = prA, cw = pcA;
                prA = prB; pcA = pcB;
                int nx = bit + 2; if (nx > 31) nx = 31;
                prB = rowp[(ib + nx) << 4];
                pcB = curp[(ib + nx) << 4];
                if (!((cur >> bit) & 1u)) {    // box ib+bit survives -> suppress
                    rem |= row;
                    cur |= cw;
                }
            }
        }
        if (lane < 16) Skw[lane] = rem;
    }
    __syncthreads();

    // Output [b, KDET, 9]; loads gated by kept (issued post-barrier)
    bool kept = !((Skw[tid >> 5] >> (tid & 31)) & 1u);
    float* orow = out + ((size_t)b * KDET + tid) * 9;
    if (kept) {
        float4 bx = g_boxes[b][tid];
        const float* r = pred + ((size_t)b * NPRED + g_six[b][tid]) * 9;
        orow[0] = bx.x; orow[1] = bx.y; orow[2] = bx.z; orow[3] = bx.w;
        orow[4] = g_ssc[b][tid];
        orow[5] = 0.0f;
        orow[6] = r[6]; orow[7] = r[7]; orow[8] = r[8];
    } else {
        #pragma unroll
        for (int q = 0; q < 9; q++) orow[q] = 0.0f;
    }
}

// ---------------------------------------------------------------------------
extern "C" void kernel_launch(void* const* d_in, const int* in_sizes, int n_in,
                              void* d_out, int out_size) {
    const float* pred = (const float*)d_in[0];
    float* out = (float*)d_out;

    score_compact_kernel<<<dim3(K1_BLKS, NB), K1_THREADS>>>(pred);
    select_sort_kernel<<<NB, 1024>>>(pred);
    mask_kernel<<<dim3(MB_SPLIT, NB), 256>>>();
    greedy_out_kernel<<<NB, KDET>>>(pred, out);
}